// round 1
// baseline (speedup 1.0000x reference)
#include <cuda_runtime.h>

// YOLO v0 loss:
//   per cell (conf, x, y, w, h):
//     obj  (t_conf > 0): 5*sum((o_i - t_i)^2, i=1..4) + (o_conf - 1)^2
//     noobj            : 0.5 * o_conf^2
//   loss = sum(...) / B,  B = 128
//
// Shapes: [B=128, W=256, H=256, C=5] fp32, contiguous, C innermost.
// Total cells = 8,388,608 (divisible by 4). 4 cells = 80 B = 5 x float4.

#define LAMBDA_COOR  5.0f
#define LAMBDA_NOOBJ 0.5f

static const int   TOTAL_CELLS = 128 * 256 * 256;
static const int   NGROUPS     = TOTAL_CELLS / 4;     // 2,097,152
static const int   BLOCK       = 256;
static const int   GRID        = NGROUPS / BLOCK;     // 8192 exactly

__device__ float g_partials[8192];

__device__ __forceinline__ float cell_loss(float o0, float o1, float o2, float o3, float o4,
                                           float t0, float t1, float t2, float t3, float t4) {
    float d1 = o1 - t1;
    float d2 = o2 - t2;
    float d3 = o3 - t3;
    float d4 = o4 - t4;
    float sq = fmaf(d1, d1, fmaf(d2, d2, fmaf(d3, d3, d4 * d4)));
    float e  = o0 - 1.0f;
    float obj   = fmaf(LAMBDA_COOR, sq, e * e);
    float noobj = LAMBDA_NOOBJ * o0 * o0;
    return (t0 > 0.0f) ? obj : noobj;
}

__global__ __launch_bounds__(BLOCK, 8)
void yolo_loss_main(const float* __restrict__ out, const float* __restrict__ tgt) {
    int g = blockIdx.x * BLOCK + threadIdx.x;

    // 5 float4 per tensor per thread = 4 cells (80 bytes), 16B-aligned since
    // group base = g * 80 bytes and cudaMalloc base is 256B-aligned.
    const float4* o4 = reinterpret_cast<const float4*>(out) + (size_t)g * 5;
    const float4* t4 = reinterpret_cast<const float4*>(tgt) + (size_t)g * 5;

    float fo[20], ft[20];
#pragma unroll
    for (int i = 0; i < 5; i++) {
        float4 a = o4[i];
        fo[4 * i + 0] = a.x; fo[4 * i + 1] = a.y; fo[4 * i + 2] = a.z; fo[4 * i + 3] = a.w;
    }
#pragma unroll
    for (int i = 0; i < 5; i++) {
        float4 b = t4[i];
        ft[4 * i + 0] = b.x; ft[4 * i + 1] = b.y; ft[4 * i + 2] = b.z; ft[4 * i + 3] = b.w;
    }

    float acc = 0.0f;
#pragma unroll
    for (int c = 0; c < 4; c++) {
        acc += cell_loss(fo[5 * c + 0], fo[5 * c + 1], fo[5 * c + 2], fo[5 * c + 3], fo[5 * c + 4],
                         ft[5 * c + 0], ft[5 * c + 1], ft[5 * c + 2], ft[5 * c + 3], ft[5 * c + 4]);
    }

    // Warp reduce
#pragma unroll
    for (int off = 16; off > 0; off >>= 1)
        acc += __shfl_down_sync(0xFFFFFFFFu, acc, off);

    __shared__ float s_warp[BLOCK / 32];
    int lane = threadIdx.x & 31;
    int wid  = threadIdx.x >> 5;
    if (lane == 0) s_warp[wid] = acc;
    __syncthreads();

    if (wid == 0) {
        float v = (lane < BLOCK / 32) ? s_warp[lane] : 0.0f;
#pragma unroll
        for (int off = 4; off > 0; off >>= 1)
            v += __shfl_down_sync(0xFFFFFFFFu, v, off);
        if (lane == 0) g_partials[blockIdx.x] = v;
    }
}

__global__ __launch_bounds__(1024, 1)
void yolo_loss_final(float* __restrict__ d_out) {
    float acc = 0.0f;
    for (int i = threadIdx.x; i < GRID; i += 1024)
        acc += g_partials[i];

#pragma unroll
    for (int off = 16; off > 0; off >>= 1)
        acc += __shfl_down_sync(0xFFFFFFFFu, acc, off);

    __shared__ float s_warp[32];
    int lane = threadIdx.x & 31;
    int wid  = threadIdx.x >> 5;
    if (lane == 0) s_warp[wid] = acc;
    __syncthreads();

    if (wid == 0) {
        float v = (lane < 32) ? s_warp[lane] : 0.0f;
#pragma unroll
        for (int off = 16; off > 0; off >>= 1)
            v += __shfl_down_sync(0xFFFFFFFFu, v, off);
        if (lane == 0) d_out[0] = v * (1.0f / 128.0f);
    }
}

extern "C" void kernel_launch(void* const* d_in, const int* in_sizes, int n_in,
                              void* d_out, int out_size) {
    const float* outputs = (const float*)d_in[0];
    const float* targets = (const float*)d_in[1];
    float* loss = (float*)d_out;

    yolo_loss_main<<<GRID, BLOCK>>>(outputs, targets);
    yolo_loss_final<<<1, 1024>>>(loss);
}

// round 2
// speedup vs baseline: 1.2253x; 1.2253x over previous
#include <cuda_runtime.h>

// YOLO v0 loss, fused single-launch version.
//   per cell (conf, x, y, w, h):
//     obj  (t_conf > 0): 5*sum((o_i - t_i)^2, i=1..4) + (o_conf - 1)^2
//     noobj            : 0.5 * o_conf^2
//   loss = sum / B,  B = 128
//
// Shapes: [128, 256, 256, 5] fp32 contiguous. 4 cells = 80 B = 5 x float4.
// Reduction: block partials -> last-arriving block folds them (deterministic,
// fixed summation order) and writes the scalar. Counter self-resets so the
// launch is CUDA-graph-replay safe.

#define LAMBDA_COOR  5.0f
#define LAMBDA_NOOBJ 0.5f

static const int TOTAL_CELLS = 128 * 256 * 256;   // 8,388,608
static const int NGROUPS     = TOTAL_CELLS / 4;   // 2,097,152 groups of 4 cells
static const int BLOCK       = 256;
static const int GRID        = NGROUPS / BLOCK;   // 8192 exactly

__device__ float        g_partials[GRID];
__device__ unsigned int g_done_count = 0;

__device__ __forceinline__ float cell_loss(float o0, float o1, float o2, float o3, float o4,
                                           float t0, float t1, float t2, float t3, float t4) {
    float d1 = o1 - t1;
    float d2 = o2 - t2;
    float d3 = o3 - t3;
    float d4 = o4 - t4;
    float sq = fmaf(d1, d1, fmaf(d2, d2, fmaf(d3, d3, d4 * d4)));
    float e  = o0 - 1.0f;
    float obj   = fmaf(LAMBDA_COOR, sq, e * e);
    float noobj = LAMBDA_NOOBJ * o0 * o0;
    return (t0 > 0.0f) ? obj : noobj;
}

__device__ __forceinline__ float block_reduce(float acc, float* s_warp) {
    // warp reduce
#pragma unroll
    for (int off = 16; off > 0; off >>= 1)
        acc += __shfl_down_sync(0xFFFFFFFFu, acc, off);
    int lane = threadIdx.x & 31;
    int wid  = threadIdx.x >> 5;
    if (lane == 0) s_warp[wid] = acc;
    __syncthreads();
    float v = 0.0f;
    if (wid == 0) {
        v = (lane < BLOCK / 32) ? s_warp[lane] : 0.0f;
#pragma unroll
        for (int off = 4; off > 0; off >>= 1)
            v += __shfl_down_sync(0xFFFFFFFFu, v, off);
    }
    return v;   // valid in thread 0 only
}

// NOTE: no minBlocksPerMultiprocessor clamp — the Round-0 version forced
// 32 regs/thread and spilled 40 live floats to local memory.
__global__ __launch_bounds__(BLOCK)
void yolo_loss_fused(const float* __restrict__ out, const float* __restrict__ tgt,
                     float* __restrict__ d_loss) {
    int g = blockIdx.x * BLOCK + threadIdx.x;

    const float4* o4 = reinterpret_cast<const float4*>(out) + (size_t)g * 5;
    const float4* t4 = reinterpret_cast<const float4*>(tgt) + (size_t)g * 5;

    // Batch all 10 streaming loads first: 10 independent LDG.E.128 in flight.
    float4 a0 = __ldcs(o4 + 0), a1 = __ldcs(o4 + 1), a2 = __ldcs(o4 + 2),
           a3 = __ldcs(o4 + 3), a4 = __ldcs(o4 + 4);
    float4 b0 = __ldcs(t4 + 0), b1 = __ldcs(t4 + 1), b2 = __ldcs(t4 + 2),
           b3 = __ldcs(t4 + 3), b4 = __ldcs(t4 + 4);

    // 4 cells per thread: channel layout across the 5 float4s:
    // cell0 = (a0.x a0.y a0.z a0.w a1.x), cell1 = (a1.y a1.z a1.w a2.x a2.y),
    // cell2 = (a2.z a2.w a3.x a3.y a3.z), cell3 = (a3.w a4.x a4.y a4.z a4.w)
    float acc;
    acc  = cell_loss(a0.x, a0.y, a0.z, a0.w, a1.x,  b0.x, b0.y, b0.z, b0.w, b1.x);
    acc += cell_loss(a1.y, a1.z, a1.w, a2.x, a2.y,  b1.y, b1.z, b1.w, b2.x, b2.y);
    acc += cell_loss(a2.z, a2.w, a3.x, a3.y, a3.z,  b2.z, b2.w, b3.x, b3.y, b3.z);
    acc += cell_loss(a3.w, a4.x, a4.y, a4.z, a4.w,  b3.w, b4.x, b4.y, b4.z, b4.w);

    __shared__ float s_warp[BLOCK / 32];
    float bsum = block_reduce(acc, s_warp);

    __shared__ bool s_is_last;
    if (threadIdx.x == 0) {
        g_partials[blockIdx.x] = bsum;
        __threadfence();                       // make partial visible chip-wide
        unsigned int n = atomicAdd(&g_done_count, 1u);
        s_is_last = (n == (unsigned int)(GRID - 1));
    }
    __syncthreads();

    if (s_is_last) {
        // Last block folds all partials. Fixed per-thread stride order ->
        // bit-identical result every call.
        float t = 0.0f;
#pragma unroll
        for (int i = threadIdx.x; i < GRID; i += BLOCK)
            t += g_partials[i];
        float total = block_reduce(t, s_warp);
        if (threadIdx.x == 0) {
            d_loss[0] = total * (1.0f / 128.0f);
            g_done_count = 0;                  // reset for next graph replay
        }
    }
}

extern "C" void kernel_launch(void* const* d_in, const int* in_sizes, int n_in,
                              void* d_out, int out_size) {
    const float* outputs = (const float*)d_in[0];
    const float* targets = (const float*)d_in[1];
    float* loss = (float*)d_out;

    yolo_loss_fused<<<GRID, BLOCK>>>(outputs, targets, loss);
}